// round 13
// baseline (speedup 1.0000x reference)
#include <cuda_runtime.h>
#include <cuda_bf16.h>
#include <cstdint>

#define T_DIM 512
#define B_DIM 128
#define E_DIM 256
#define U_DIM 256

// Scratch for xW[t][b][u]  (64 MB fp32 — L2-resident)
__device__ float g_xw[T_DIM * B_DIM * U_DIM];

// ---------------- helpers ----------------
__device__ __forceinline__ uint32_t smem_u32(const void* p) {
    uint32_t a;
    asm("{ .reg .u64 t; cvta.to.shared.u64 t, %1; cvt.u32.u64 %0, t; }" : "=r"(a) : "l"(p));
    return a;
}
__device__ __forceinline__ uint32_t packbf(float a, float b) {
    __nv_bfloat162 t = __floats2bfloat162_rn(a, b);
    return *reinterpret_cast<uint32_t*>(&t);
}
__device__ __forceinline__ void ldsm_x4(uint32_t* r, uint32_t addr) {
    asm volatile("ldmatrix.sync.aligned.m8n8.x4.shared.b16 {%0,%1,%2,%3}, [%4];"
                 : "=r"(r[0]), "=r"(r[1]), "=r"(r[2]), "=r"(r[3]) : "r"(addr));
}
__device__ __forceinline__ void ldsm_x2(uint32_t* r, uint32_t addr) {
    asm volatile("ldmatrix.sync.aligned.m8n8.x2.shared.b16 {%0,%1}, [%2];"
                 : "=r"(r[0]), "=r"(r[1]) : "r"(addr));
}
__device__ __forceinline__ void mma_bf16(float* c, const uint32_t* a, const uint32_t* b) {
    asm volatile("mma.sync.aligned.m16n8k16.row.col.f32.bf16.bf16.f32 "
                 "{%0,%1,%2,%3}, {%4,%5,%6,%7}, {%8,%9}, {%0,%1,%2,%3};"
                 : "+f"(c[0]), "+f"(c[1]), "+f"(c[2]), "+f"(c[3])
                 : "r"(a[0]), "r"(a[1]), "r"(a[2]), "r"(a[3]), "r"(b[0]), "r"(b[1]));
}
__device__ __forceinline__ void cpasync16(uint32_t dst, const void* src) {
    asm volatile("cp.async.ca.shared.global [%0], [%1], 16;" :: "r"(dst), "l"(src) : "memory");
}

// mbarrier try_wait with cluster-scope acquire (sees peer DSMEM stores)
#define MBAR_WAIT_CL(mb, parity) do { \
    uint32_t _m = (mb); uint32_t _p = (parity); uint32_t _d; \
    asm volatile("{\n\t.reg .pred p;\n\t" \
        "mbarrier.try_wait.parity.acquire.cluster.shared::cta.b64 p, [%1], %2;\n\t" \
        "selp.b32 %0, 1, 0, p;\n\t}" : "=r"(_d) : "r"(_m), "r"(_p) : "memory"); \
    if (!_d) { \
        asm volatile("{\n\t.reg .pred P1;\n\t" \
            "WL_%=:\n\t" \
            "mbarrier.try_wait.parity.acquire.cluster.shared::cta.b64 P1, [%0], %1, 0x989680;\n\t" \
            "@P1 bra.uni WD_%=;\n\t" \
            "bra.uni WL_%=;\n\t" \
            "WD_%=:\n\t}" :: "r"(_m), "r"(_p) : "memory"); \
    } } while (0)

// ---------------- Kernel 1: xW[t][b][u] = emb[token(b,t)] . W[u] ----------------
static constexpr int APAD = 264;
static constexpr int AS_OFF = 0;
static constexpr int BS_OFF = 128 * APAD * 2;
static constexpr int XW_SMEM = BS_OFF + 256 * APAD * 2;

__global__ void __launch_bounds__(256, 1)
xw_kernel(const int* __restrict__ sentence, const float* __restrict__ emb,
          const float* __restrict__ W) {
    extern __shared__ char smem[];
    const int tid = threadIdx.x, t = blockIdx.x;
    const int wid = tid >> 5, lane = tid & 31;
    const uint32_t sb = smem_u32(smem);

    {
        const int sub = tid & 7;
        #pragma unroll
        for (int p = 0; p < 4; p++) {
            const int r = p * 32 + (tid >> 3);
            const int tok = sentence[r * T_DIM + t];
            const float4* src = reinterpret_cast<const float4*>(emb + (size_t)tok * E_DIM) + sub;
            char* dstrow = smem + AS_OFF + r * (APAD * 2);
            #pragma unroll
            for (int j = 0; j < 8; j++) {
                float4 v = src[j * 8];
                *reinterpret_cast<uint2*>(dstrow + (sub + j * 8) * 8) =
                    make_uint2(packbf(v.x, v.y), packbf(v.z, v.w));
            }
        }
    }
    {
        const int sub = tid & 7;
        #pragma unroll
        for (int p = 0; p < 8; p++) {
            const int r = p * 32 + (tid >> 3);
            const float4* src = reinterpret_cast<const float4*>(W + (size_t)r * E_DIM) + sub;
            char* dstrow = smem + BS_OFF + r * (APAD * 2);
            #pragma unroll
            for (int j = 0; j < 8; j++) {
                float4 v = src[j * 8];
                *reinterpret_cast<uint2*>(dstrow + (sub + j * 8) * 8) =
                    make_uint2(packbf(v.x, v.y), packbf(v.z, v.w));
            }
        }
    }
    __syncthreads();

    const int m0 = wid * 16;
    float c[32][4];
    #pragma unroll
    for (int j = 0; j < 32; j++) { c[j][0] = c[j][1] = c[j][2] = c[j][3] = 0.f; }

    const uint32_t a_addr = sb + AS_OFF + (m0 + (lane & 15)) * (APAD * 2) + (lane >> 4) * 16;
    const uint32_t b_addr = sb + BS_OFF + (lane & 7) * (APAD * 2) + ((lane >> 3) & 1) * 16;

    for (int k = 0; k < 16; k++) {
        uint32_t a[4];
        ldsm_x4(a, a_addr + k * 32);
        #pragma unroll
        for (int j = 0; j < 32; j++) {
            uint32_t b[2];
            ldsm_x2(b, b_addr + j * 8 * (APAD * 2) + k * 32);
            mma_bf16(c[j], a, b);
        }
    }

    float* outp = g_xw + (size_t)t * (B_DIM * U_DIM);
    const int r0 = m0 + (lane >> 2), c0 = (lane & 3) * 2;
    #pragma unroll
    for (int j = 0; j < 32; j++) {
        const int col = j * 8 + c0;
        *reinterpret_cast<float2*>(outp + r0 * U_DIM + col)       = make_float2(c[j][0], c[j][1]);
        *reinterpret_cast<float2*>(outp + (r0 + 8) * U_DIM + col) = make_float2(c[j][2], c[j][3]);
    }
}

// ---------------- Kernel 2: cluster-2 u-split tensor-core recurrence ----------------
// 32 CTAs = 16 clusters x 2. Cluster = one 8-row batch tile; rank owns u-half 128.
// 512 thr: warps 0-7 (kh=0) k[0:128), warps 8-15 (kh=1) k[128:256), same u-tiles.
// Per warp: 4 ldsm + 8 HMMA (4 chains depth 2). k-halves merged via smem partials.
// Warps 0-7 epilogue: +xw, tanh, movmatrix, store h half local + peer (DSMEM).
// Step sync: bar -> thread0 mbarrier.arrive.release.cluster on peer -> all
// try_wait.parity.acquire.cluster on own mbar. Warps 8-15 stage xw via cp.async.

static constexpr int HSTRIDE = 528;                  // bytes per b-row (264 bf16)
static constexpr int HBUF    = 8 * HSTRIDE;          // 4224 per buffer

__global__ void __launch_bounds__(512, 1) __cluster_dims__(2, 1, 1)
rnn_kernel(const float* __restrict__ Um, const float* __restrict__ W1,
           const float* __restrict__ b1, const float* __restrict__ W2,
           const float* __restrict__ b2, float* __restrict__ out) {
    __shared__ __align__(16) char hbuf[2 * HBUF];
    __shared__ __align__(16) float xws[2 * 8 * 128];     // xw stage: our u-half only
    __shared__ __align__(16) float pbuf[8 * 32 * 4];     // k-half partials
    __shared__ __align__(16) float hfin[8 * 256];
    __shared__ float hid[8 * 32];
    __shared__ __align__(8) unsigned long long mbar;

    const int tid = threadIdx.x, wid = tid >> 5, lane = tid & 31;
    const int rank = blockIdx.x & 1;
    const int b0   = (blockIdx.x >> 1) * 8;
    const int w8 = wid & 7, kh = wid >> 3;
    const int u0 = rank * 128 + w8 * 16;      // global u base of this warp's tile
    const int r = lane >> 2, q = lane & 3;

    // ---- U fragments (this warp's k-half) into registers ----
    uint32_t ua[32];
    #pragma unroll
    for (int kt = 0; kt < 8; kt++) {
        const int ktg = kh * 8 + kt;
        const float2* p0 = reinterpret_cast<const float2*>(Um + (size_t)(u0 + r) * U_DIM + ktg * 16 + 2 * q);
        const float2* p1 = reinterpret_cast<const float2*>(Um + (size_t)(u0 + r + 8) * U_DIM + ktg * 16 + 2 * q);
        float2 v0 = p0[0], v1 = p1[0], v2 = p0[4], v3 = p1[4];
        ua[kt * 4 + 0] = packbf(v0.x, v0.y);
        ua[kt * 4 + 1] = packbf(v1.x, v1.y);
        ua[kt * 4 + 2] = packbf(v2.x, v2.y);
        ua[kt * 4 + 3] = packbf(v3.x, v3.y);
    }

    for (int i = tid; i < (2 * HBUF) / 4; i += 512)
        reinterpret_cast<uint32_t*>(hbuf)[i] = 0;
    if (tid == 0)
        asm volatile("mbarrier.init.shared.b64 [%0], 1;" :: "r"(smem_u32(&mbar)) : "memory");

    // prologue: stage xw(0) (warps 8-15; our u-half, 4KB)
    const uint32_t xw_smem = smem_u32(xws);
    if (tid >= 256) {
        const int t2 = tid - 256, bb = t2 >> 5, j = t2 & 31;
        cpasync16(xw_smem + bb * 512 + j * 16,
                  g_xw + (size_t)(b0 + bb) * U_DIM + rank * 128 + j * 4);
    }
    asm volatile("cp.async.commit_group;" ::: "memory");
    asm volatile("cp.async.wait_group 0;" ::: "memory");
    __syncthreads();
    asm volatile("barrier.cluster.arrive.aligned;" ::: "memory");   // mbar init visible
    asm volatile("barrier.cluster.wait.aligned;" ::: "memory");

    const uint32_t hb = smem_u32(hbuf);
    const uint32_t mb = smem_u32(&mbar);
    uint32_t hb_peer, mb_peer, hfin_r0;
    {
        const uint32_t pr = rank ^ 1;
        asm("mapa.shared::cluster.u32 %0, %1, %2;" : "=r"(hb_peer) : "r"(hb), "r"(pr));
        asm("mapa.shared::cluster.u32 %0, %1, %2;" : "=r"(mb_peer) : "r"(mb), "r"(pr));
        asm("mapa.shared::cluster.u32 %0, %1, %2;" : "=r"(hfin_r0) : "r"(smem_u32(hfin)), "r"(0u));
    }

    const uint32_t rd0 = hb + (lane & 7) * HSTRIDE + (lane >> 3) * 16 + kh * 256;
    const uint32_t so0 = r * HSTRIDE + (u0 + 2 * q) * 2;
    const int xo = (2 * q) * 128 + w8 * 16 + r;
    float* pslot = pbuf + (w8 * 32 + lane) * 4;

    for (int t = 0; t < T_DIM; t++) {
        if (tid >= 256 && t + 1 < T_DIM) {               // stage xw(t+1)
            const int t2 = tid - 256, bb = t2 >> 5, j = t2 & 31;
            cpasync16(xw_smem + ((t + 1) & 1) * 4096 + bb * 512 + j * 16,
                      g_xw + (size_t)(t + 1) * (B_DIM * U_DIM)
                           + (size_t)(b0 + bb) * U_DIM + rank * 128 + j * 4);
        }
        asm volatile("cp.async.commit_group;" ::: "memory");

        const uint32_t rb = rd0 + (t & 1) * HBUF;
        float c0[4] = {0,0,0,0}, c1[4] = {0,0,0,0}, c2[4] = {0,0,0,0}, c3[4] = {0,0,0,0};
        #pragma unroll
        for (int kb = 0; kb < 4; kb++) {
            uint32_t bq[4];
            ldsm_x4(bq, rb + kb * 64);
            if (kb & 1) { mma_bf16(c2, ua + kb * 8, bq); mma_bf16(c3, ua + kb * 8 + 4, bq + 2); }
            else        { mma_bf16(c0, ua + kb * 8, bq); mma_bf16(c1, ua + kb * 8 + 4, bq + 2); }
        }
        float m0 = (c0[0] + c1[0]) + (c2[0] + c3[0]);
        float m1 = (c0[1] + c1[1]) + (c2[1] + c3[1]);
        float m2 = (c0[2] + c1[2]) + (c2[2] + c3[2]);
        float m3 = (c0[3] + c1[3]) + (c2[3] + c3[3]);

        if (kh) *reinterpret_cast<float4*>(pslot) = make_float4(m0, m1, m2, m3);
        __syncthreads();                                 // partials visible

        if (!kh) {
            const float* xs = xws + (t & 1) * (8 * 128) + xo;
            float4 pp = *reinterpret_cast<const float4*>(pslot);
            float h0 = m0 + pp.x + xs[0];
            float h1 = m1 + pp.y + xs[128];
            float h2 = m2 + pp.z + xs[8];
            float h3 = m3 + pp.w + xs[136];
            asm("tanh.approx.f32 %0, %1;" : "=f"(h0) : "f"(h0));
            asm("tanh.approx.f32 %0, %1;" : "=f"(h1) : "f"(h1));
            asm("tanh.approx.f32 %0, %1;" : "=f"(h2) : "f"(h2));
            asm("tanh.approx.f32 %0, %1;" : "=f"(h3) : "f"(h3));

            if (t == T_DIM - 1) {                        // fp32 h -> rank0 hfin
                const uint32_t fo = hfin_r0 + (uint32_t)(((2 * q) * 256 + u0 + r) * 4);
                asm volatile("st.shared::cluster.b32 [%0], %1;" :: "r"(fo),        "r"(__float_as_uint(h0)));
                asm volatile("st.shared::cluster.b32 [%0], %1;" :: "r"(fo + 1024), "r"(__float_as_uint(h1)));
                asm volatile("st.shared::cluster.b32 [%0], %1;" :: "r"(fo + 32),   "r"(__float_as_uint(h2)));
                asm volatile("st.shared::cluster.b32 [%0], %1;" :: "r"(fo + 1056), "r"(__float_as_uint(h3)));
            }

            uint32_t g0 = packbf(h0, h1), g1 = packbf(h2, h3);
            uint32_t t0, t1;
            asm("movmatrix.sync.aligned.m8n8.trans.b16 %0, %1;" : "=r"(t0) : "r"(g0));
            asm("movmatrix.sync.aligned.m8n8.trans.b16 %0, %1;" : "=r"(t1) : "r"(g1));

            const uint32_t woff = (uint32_t)(((t & 1) ^ 1) * HBUF) + so0;
            asm volatile("st.shared::cluster.b32 [%0], %1;" :: "r"(hb_peer + woff),      "r"(t0));
            asm volatile("st.shared::cluster.b32 [%0], %1;" :: "r"(hb_peer + woff + 16), "r"(t1));
            asm volatile("st.shared.b32 [%0], %1;" :: "r"(hb + woff),      "r"(t0));
            asm volatile("st.shared.b32 [%0], %1;" :: "r"(hb + woff + 16), "r"(t1));
        }

        asm volatile("cp.async.wait_group 0;" ::: "memory");
        __syncthreads();                                 // local h + xw visible
        if (tid == 0)
            asm volatile("mbarrier.arrive.release.cluster.shared::cluster.b64 _, [%0];"
                         :: "r"(mb_peer) : "memory");
        MBAR_WAIT_CL(mb, t & 1);                         // peer data visible
    }

    asm volatile("barrier.cluster.arrive.aligned;" ::: "memory");
    asm volatile("barrier.cluster.wait.aligned;" ::: "memory");

    // ---- head on rank 0 (full fp32 hfin) ----
    if (rank == 0) {
        if (tid < 256) {
            const int rr = tid >> 5, j = tid & 31;
            float a = b1[j];
            #pragma unroll 8
            for (int k = 0; k < 256; k++) a = fmaf(hfin[rr * 256 + k], W1[k * 32 + j], a);
            hid[rr * 32 + j] = fmaxf(a, 0.0f);
        }
        __syncthreads();
        if (tid < 8) {
            float l0 = b2[0], l1 = b2[1];
            #pragma unroll
            for (int j = 0; j < 32; j++) {
                float x = hid[tid * 32 + j];
                l0 += x * W2[j * 2 + 0];
                l1 += x * W2[j * 2 + 1];
            }
            float mx = fmaxf(l0, l1);
            float e0 = __expf(l0 - mx), e1 = __expf(l1 - mx);
            float inv = 1.0f / (e0 + e1);
            out[(b0 + tid) * 2 + 0] = e0 * inv;
            out[(b0 + tid) * 2 + 1] = e1 * inv;
        }
    }
}

// ---------------- launch ----------------
extern "C" void kernel_launch(void* const* d_in, const int* in_sizes, int n_in,
                              void* d_out, int out_size) {
    const int*   sentence = (const int*)  d_in[0];
    const float* emb      = (const float*)d_in[1];
    const float* W        = (const float*)d_in[2];
    const float* Um       = (const float*)d_in[3];
    const float* W1       = (const float*)d_in[4];
    const float* b1       = (const float*)d_in[5];
    const float* W2       = (const float*)d_in[6];
    const float* b2       = (const float*)d_in[7];
    float* out = (float*)d_out;

    cudaFuncSetAttribute(xw_kernel, cudaFuncAttributeMaxDynamicSharedMemorySize, XW_SMEM);

    xw_kernel<<<T_DIM, 256, XW_SMEM>>>(sentence, emb, W);
    rnn_kernel<<<B_DIM / 8 * 2, 512>>>(Um, W1, b1, W2, b2, out);
}

// round 14
// speedup vs baseline: 1.3164x; 1.3164x over previous
#include <cuda_runtime.h>
#include <cuda_bf16.h>
#include <cstdint>

#define T_DIM 512
#define B_DIM 128
#define E_DIM 256
#define U_DIM 256

// Scratch for xW[t][b][u]  (64 MB fp32 — L2-resident)
__device__ float g_xw[T_DIM * B_DIM * U_DIM];

// ---------------- helpers ----------------
__device__ __forceinline__ uint32_t smem_u32(const void* p) {
    uint32_t a;
    asm("{ .reg .u64 t; cvta.to.shared.u64 t, %1; cvt.u32.u64 %0, t; }" : "=r"(a) : "l"(p));
    return a;
}
__device__ __forceinline__ uint32_t packbf(float a, float b) {
    __nv_bfloat162 t = __floats2bfloat162_rn(a, b);
    return *reinterpret_cast<uint32_t*>(&t);
}
__device__ __forceinline__ void ldsm_x4(uint32_t* r, uint32_t addr) {
    asm volatile("ldmatrix.sync.aligned.m8n8.x4.shared.b16 {%0,%1,%2,%3}, [%4];"
                 : "=r"(r[0]), "=r"(r[1]), "=r"(r[2]), "=r"(r[3]) : "r"(addr));
}
__device__ __forceinline__ void ldsm_x2(uint32_t* r, uint32_t addr) {
    asm volatile("ldmatrix.sync.aligned.m8n8.x2.shared.b16 {%0,%1}, [%2];"
                 : "=r"(r[0]), "=r"(r[1]) : "r"(addr));
}
__device__ __forceinline__ void mma_bf16(float* c, const uint32_t* a, const uint32_t* b) {
    asm volatile("mma.sync.aligned.m16n8k16.row.col.f32.bf16.bf16.f32 "
                 "{%0,%1,%2,%3}, {%4,%5,%6,%7}, {%8,%9}, {%0,%1,%2,%3};"
                 : "+f"(c[0]), "+f"(c[1]), "+f"(c[2]), "+f"(c[3])
                 : "r"(a[0]), "r"(a[1]), "r"(a[2]), "r"(a[3]), "r"(b[0]), "r"(b[1]));
}
__device__ __forceinline__ void cpasync16(uint32_t dst, const void* src) {
    asm volatile("cp.async.ca.shared.global [%0], [%1], 16;" :: "r"(dst), "l"(src) : "memory");
}

// ---------------- Kernel 1: xW[t][b][u] = emb[token(b,t)] . W[u] ----------------
static constexpr int APAD = 264;
static constexpr int AS_OFF = 0;
static constexpr int BS_OFF = 128 * APAD * 2;
static constexpr int XW_SMEM = BS_OFF + 256 * APAD * 2;

__global__ void __launch_bounds__(256, 1)
xw_kernel(const int* __restrict__ sentence, const float* __restrict__ emb,
          const float* __restrict__ W) {
    extern __shared__ char smem[];
    const int tid = threadIdx.x, t = blockIdx.x;
    const int wid = tid >> 5, lane = tid & 31;
    const uint32_t sb = smem_u32(smem);

    {
        const int sub = tid & 7;
        #pragma unroll
        for (int p = 0; p < 4; p++) {
            const int r = p * 32 + (tid >> 3);
            const int tok = sentence[r * T_DIM + t];
            const float4* src = reinterpret_cast<const float4*>(emb + (size_t)tok * E_DIM) + sub;
            char* dstrow = smem + AS_OFF + r * (APAD * 2);
            #pragma unroll
            for (int j = 0; j < 8; j++) {
                float4 v = src[j * 8];
                *reinterpret_cast<uint2*>(dstrow + (sub + j * 8) * 8) =
                    make_uint2(packbf(v.x, v.y), packbf(v.z, v.w));
            }
        }
    }
    {
        const int sub = tid & 7;
        #pragma unroll
        for (int p = 0; p < 8; p++) {
            const int r = p * 32 + (tid >> 3);
            const float4* src = reinterpret_cast<const float4*>(W + (size_t)r * E_DIM) + sub;
            char* dstrow = smem + BS_OFF + r * (APAD * 2);
            #pragma unroll
            for (int j = 0; j < 8; j++) {
                float4 v = src[j * 8];
                *reinterpret_cast<uint2*>(dstrow + (sub + j * 8) * 8) =
                    make_uint2(packbf(v.x, v.y), packbf(v.z, v.w));
            }
        }
    }
    __syncthreads();

    const int m0 = wid * 16;
    float c[32][4];
    #pragma unroll
    for (int j = 0; j < 32; j++) { c[j][0] = c[j][1] = c[j][2] = c[j][3] = 0.f; }

    const uint32_t a_addr = sb + AS_OFF + (m0 + (lane & 15)) * (APAD * 2) + (lane >> 4) * 16;
    const uint32_t b_addr = sb + BS_OFF + (lane & 7) * (APAD * 2) + ((lane >> 3) & 1) * 16;

    for (int k = 0; k < 16; k++) {
        uint32_t a[4];
        ldsm_x4(a, a_addr + k * 32);
        #pragma unroll
        for (int j = 0; j < 32; j++) {
            uint32_t b[2];
            ldsm_x2(b, b_addr + j * 8 * (APAD * 2) + k * 32);
            mma_bf16(c[j], a, b);
        }
    }

    float* outp = g_xw + (size_t)t * (B_DIM * U_DIM);
    const int r0 = m0 + (lane >> 2), c0 = (lane & 3) * 2;
    #pragma unroll
    for (int j = 0; j < 32; j++) {
        const int col = j * 8 + c0;
        *reinterpret_cast<float2*>(outp + r0 * U_DIM + col)       = make_float2(c[j][0], c[j][1]);
        *reinterpret_cast<float2*>(outp + (r0 + 8) * U_DIM + col) = make_float2(c[j][2], c[j][3]);
    }
}

// ---------------- Kernel 2: intra-CTA k-split tensor-core recurrence ----------------
// 16 CTAs x 8 batch rows, 1024 threads (32 warps). Warp (uw = wid&15, kh = wid>>4)
// computes u-tile [16*uw,16*uw+16) over k-half [128*kh, 128*kh+128).
// A = U in registers (32 regs/warp); B = h (bf16 smem, double-buffered), 4 ldsm;
// 8 HMMA in two depth-4 chains. kh=1 warps write float4 partials + bar.arrive;
// kh=0 warps bar.sync, merge, +xw, tanh, movmatrix-transpose, store h.
// xw staged per-step into double-buffered smem by kh=1 threads via cp.async.

static constexpr int HSTRIDE = 528;                  // bytes per b-row (264 bf16)
static constexpr int HBUF    = 8 * HSTRIDE;          // 4224 per buffer

__global__ void __launch_bounds__(1024, 1)
rnn_kernel(const float* __restrict__ Um, const float* __restrict__ W1,
           const float* __restrict__ b1, const float* __restrict__ W2,
           const float* __restrict__ b2, float* __restrict__ out) {
    __shared__ __align__(16) char hbuf[2 * HBUF];
    __shared__ __align__(16) float xws[2 * 8 * 256];     // xw stage (8KB x2)
    __shared__ __align__(16) float pbuf[16 * 32 * 4];    // k-half partials (8KB)
    __shared__ __align__(16) float hfin[8 * 256];
    __shared__ float hid[8 * 32];

    const int tid = threadIdx.x, wid = tid >> 5, lane = tid & 31;
    const int b0 = blockIdx.x * 8;
    const int uw = wid & 15, kh = wid >> 4;
    const int u0 = uw * 16;
    const int r = lane >> 2, q = lane & 3;

    // ---- U fragments (this warp's k-half) into registers ----
    uint32_t ua[32];
    #pragma unroll
    for (int kt = 0; kt < 8; kt++) {
        const int ktg = kh * 8 + kt;
        const float2* p0 = reinterpret_cast<const float2*>(Um + (size_t)(u0 + r) * U_DIM + ktg * 16 + 2 * q);
        const float2* p1 = reinterpret_cast<const float2*>(Um + (size_t)(u0 + r + 8) * U_DIM + ktg * 16 + 2 * q);
        float2 v0 = p0[0], v1 = p1[0], v2 = p0[4], v3 = p1[4];
        ua[kt * 4 + 0] = packbf(v0.x, v0.y);
        ua[kt * 4 + 1] = packbf(v1.x, v1.y);
        ua[kt * 4 + 2] = packbf(v2.x, v2.y);
        ua[kt * 4 + 3] = packbf(v3.x, v3.y);
    }

    for (int i = tid; i < (2 * HBUF) / 4; i += 1024)
        reinterpret_cast<uint32_t*>(hbuf)[i] = 0;

    // prologue: stage xw(0) into buffer 0 (threads 512..1023, 16B each)
    const uint32_t xw_smem = smem_u32(xws);
    if (tid >= 512) {
        const int t2 = tid - 512;
        cpasync16(xw_smem + t2 * 16,
                  reinterpret_cast<const char*>(g_xw + (size_t)b0 * U_DIM) + t2 * 16);
    }
    asm volatile("cp.async.commit_group;" ::: "memory");
    if (tid >= 512) asm volatile("cp.async.wait_group 0;" ::: "memory");
    __syncthreads();

    const uint32_t hb = smem_u32(hbuf);
    const uint32_t rd0 = hb + (lane & 7) * HSTRIDE + (lane >> 3) * 16 + kh * 256;
    const uint32_t so0 = r * HSTRIDE + (u0 + 2 * q) * 2;
    const int xo = (2 * q) * 256 + u0 + r;
    float4* pslot = reinterpret_cast<float4*>(pbuf + (uw * 32 + lane) * 4);

    for (int t = 0; t < T_DIM; t++) {
        if (tid >= 512 && t + 1 < T_DIM) {               // stage xw(t+1)
            const int t2 = tid - 512;
            cpasync16(xw_smem + ((t + 1) & 1) * 8192 + t2 * 16,
                      reinterpret_cast<const char*>(
                          g_xw + (size_t)(t + 1) * (B_DIM * U_DIM) + (size_t)b0 * U_DIM) + t2 * 16);
        }
        asm volatile("cp.async.commit_group;" ::: "memory");

        const uint32_t rb = rd0 + (t & 1) * HBUF;
        float c0[4] = {0,0,0,0}, c1[4] = {0,0,0,0};
        #pragma unroll
        for (int kb = 0; kb < 4; kb++) {
            uint32_t bq[4];
            ldsm_x4(bq, rb + kb * 64);
            mma_bf16(c0, ua + kb * 8,     bq);           // chain 0 (depth 4)
            mma_bf16(c1, ua + kb * 8 + 4, bq + 2);       // chain 1 (depth 4)
        }
        const float m0 = c0[0] + c1[0], m1 = c0[1] + c1[1];
        const float m2 = c0[2] + c1[2], m3 = c0[3] + c1[3];

        if (kh) {
            *pslot = make_float4(m0, m1, m2, m3);
            asm volatile("bar.arrive 1, 1024;" ::: "memory");
            asm volatile("cp.async.wait_group 0;" ::: "memory");
        } else {
            asm volatile("bar.sync 1, 1024;" ::: "memory");
            const float* xs = xws + (t & 1) * (8 * 256) + xo;
            float4 pp = *pslot;
            float h0 = m0 + pp.x + xs[0];
            float h1 = m1 + pp.y + xs[256];
            float h2 = m2 + pp.z + xs[8];
            float h3 = m3 + pp.w + xs[264];
            asm("tanh.approx.f32 %0, %1;" : "=f"(h0) : "f"(h0));
            asm("tanh.approx.f32 %0, %1;" : "=f"(h1) : "f"(h1));
            asm("tanh.approx.f32 %0, %1;" : "=f"(h2) : "f"(h2));
            asm("tanh.approx.f32 %0, %1;" : "=f"(h3) : "f"(h3));

            if (t == T_DIM - 1) {                        // fp32 h for the head
                hfin[(2 * q) * 256 + u0 + r]         = h0;
                hfin[(2 * q + 1) * 256 + u0 + r]     = h1;
                hfin[(2 * q) * 256 + u0 + r + 8]     = h2;
                hfin[(2 * q + 1) * 256 + u0 + r + 8] = h3;
            }

            uint32_t g0 = packbf(h0, h1), g1 = packbf(h2, h3);
            uint32_t t0, t1;                             // transpose (u,b) -> (b,u)
            asm("movmatrix.sync.aligned.m8n8.trans.b16 %0, %1;" : "=r"(t0) : "r"(g0));
            asm("movmatrix.sync.aligned.m8n8.trans.b16 %0, %1;" : "=r"(t1) : "r"(g1));

            const uint32_t wa = hb + (uint32_t)(((t & 1) ^ 1) * HBUF) + so0;
            asm volatile("st.shared.b32 [%0], %1;" :: "r"(wa),      "r"(t0));
            asm volatile("st.shared.b32 [%0], %1;" :: "r"(wa + 16), "r"(t1));
        }
        __syncthreads();                                 // h(t+1) + xw(t+1) visible
    }

    // ---- head: hidden = relu(hfin @ W1 + b1); logits -> softmax ----
    if (tid < 256) {                       // 8 rows x 32 units
        const int rr = tid >> 5, j = tid & 31;
        float a = b1[j];
        #pragma unroll 8
        for (int k = 0; k < 256; k++) a = fmaf(hfin[rr * 256 + k], W1[k * 32 + j], a);
        hid[rr * 32 + j] = fmaxf(a, 0.0f);
    }
    __syncthreads();
    if (tid < 8) {
        float l0 = b2[0], l1 = b2[1];
        #pragma unroll
        for (int j = 0; j < 32; j++) {
            float x = hid[tid * 32 + j];
            l0 += x * W2[j * 2 + 0];
            l1 += x * W2[j * 2 + 1];
        }
        float mx = fmaxf(l0, l1);
        float e0 = __expf(l0 - mx), e1 = __expf(l1 - mx);
        float inv = 1.0f / (e0 + e1);
        out[(b0 + tid) * 2 + 0] = e0 * inv;
        out[(b0 + tid) * 2 + 1] = e1 * inv;
    }
}

// ---------------- launch ----------------
extern "C" void kernel_launch(void* const* d_in, const int* in_sizes, int n_in,
                              void* d_out, int out_size) {
    const int*   sentence = (const int*)  d_in[0];
    const float* emb      = (const float*)d_in[1];
    const float* W        = (const float*)d_in[2];
    const float* Um       = (const float*)d_in[3];
    const float* W1       = (const float*)d_in[4];
    const float* b1       = (const float*)d_in[5];
    const float* W2       = (const float*)d_in[6];
    const float* b2       = (const float*)d_in[7];
    float* out = (float*)d_out;

    cudaFuncSetAttribute(xw_kernel, cudaFuncAttributeMaxDynamicSharedMemorySize, XW_SMEM);

    xw_kernel<<<T_DIM, 256, XW_SMEM>>>(sentence, emb, W);
    rnn_kernel<<<B_DIM / 8, 1024>>>(Um, W1, b1, W2, b2, out);
}